// round 16
// baseline (speedup 1.0000x reference)
#include <cuda_runtime.h>
#include <stdint.h>

#define BB 4
#define CC 256
#define DQK 32
#define NN 4096
#define TQ 128          // queries per CTA
#define KT 32           // keys per tile
#define NKT (NN / KT)   // 128
#define THREADS 512

// ---------------- global scratch ----------------
__device__ float g_qh[BB * NN * DQK];   // Q tf32-hi [b][n][d]
__device__ float g_ql[BB * NN * DQK];   // Q tf32-lo
__device__ float g_kh[BB * NN * DQK];   // K tf32-hi [b][m][d]
__device__ float g_kl[BB * NN * DQK];   // K tf32-lo
__device__ float g_vT[BB * CC * NN];    // V^T tf32-rounded [b][c][m]

// ---------------- helpers ----------------
__device__ __forceinline__ uint32_t f2tf32(float f) {
    uint32_t u; asm("cvt.rna.tf32.f32 %0, %1;" : "=r"(u) : "f"(f)); return u;
}
__device__ __forceinline__ uint32_t smem_u32(const void* p) {
    uint32_t a;
    asm("{ .reg .u64 t; cvta.to.shared.u64 t, %1; cvt.u32.u64 %0, t; }" : "=r"(a) : "l"(p));
    return a;
}
__device__ __forceinline__ void cp16(uint32_t dst, const float* src) {
    asm volatile("cp.async.cg.shared.global [%0], [%1], 16;" :: "r"(dst), "l"(src));
}
#define CP_COMMIT() asm volatile("cp.async.commit_group;" ::: "memory")
#define CP_WAIT0()  asm volatile("cp.async.wait_group 0;" ::: "memory")
#define CP_WAIT1()  asm volatile("cp.async.wait_group 1;" ::: "memory")

__device__ __forceinline__ void mma_tf32(float d[4],
    uint32_t a0, uint32_t a1, uint32_t a2, uint32_t a3,
    uint32_t b0, uint32_t b1)
{
    asm volatile(
        "mma.sync.aligned.m16n8k8.row.col.f32.tf32.tf32.f32 "
        "{%0,%1,%2,%3},{%4,%5,%6,%7},{%8,%9},{%0,%1,%2,%3};"
        : "+f"(d[0]), "+f"(d[1]), "+f"(d[2]), "+f"(d[3])
        : "r"(a0), "r"(a1), "r"(a2), "r"(a3), "r"(b0), "r"(b1));
}
__device__ __forceinline__ void ldm_x4(uint32_t& r0, uint32_t& r1,
                                       uint32_t& r2, uint32_t& r3, uint32_t addr)
{
    asm volatile("ldmatrix.sync.aligned.m8n8.x4.shared.b16 {%0,%1,%2,%3}, [%4];"
        : "=r"(r0), "=r"(r1), "=r"(r2), "=r"(r3) : "r"(addr));
}

// ---------------- smem layout (word offsets) ----------------
// All operand planes are fragment-packed: one 8x4-word matrix = 128 B block.
#define OFF_QLO    0                            // 4096 w
#define OFF_KH(bf) (4096 + (bf) * 2048)         // 1024 w per plane
#define OFF_KL(bf) (4096 + (bf) * 2048 + 1024)
#define OFF_P(bf)  (8192 + (bf) * 4096)         // 4096 w
#define OFF_V(bf)  (16384 + (bf) * 8192)        // 8192 w, 3 buffers
#define OFF_LSUM   40960                        // 256 w
#define SMEM_FLOATS 41216                       // 164864 bytes

// ---------------------------------------------------------------------------
// proj_qk: hi/lo tf32 split planes [b][n][32]
// ---------------------------------------------------------------------------
__global__ __launch_bounds__(256) void proj_qk(
    const float* __restrict__ X, const float* __restrict__ W,
    const float* __restrict__ bias,
    float* __restrict__ o_hi, float* __restrict__ o_lo)
{
    const int b  = blockIdx.z;
    const int n0 = blockIdx.x * 128;
    const int t  = threadIdx.x;
    const int tx = t & 31;
    const int ty = t >> 5;

    __shared__ float As[32][128];
    __shared__ float Bs[32][32];

    float acc[4][4];
#pragma unroll
    for (int i = 0; i < 4; i++)
#pragma unroll
        for (int u = 0; u < 4; u++) acc[i][u] = 0.f;

    const float* Xb = X + b * CC * NN;
    for (int c0 = 0; c0 < CC; c0 += 32) {
#pragma unroll
        for (int i = 0; i < 4; i++) {
            int idx = t + 256 * i;
            int cc  = idx >> 5;
            int nn  = (idx & 31) * 4;
            *(float4*)&As[cc][nn] = *(const float4*)(Xb + (c0 + cc) * NN + n0 + nn);
        }
        {
            int jj = t >> 3;
            int c4 = (t & 7) * 4;
            *(float4*)&Bs[jj][c4] = *(const float4*)(W + jj * CC + c0 + c4);
        }
        __syncthreads();
#pragma unroll
        for (int cc = 0; cc < 32; cc++) {
            float4 a = *(const float4*)&As[cc][tx * 4];
            float b0 = Bs[ty * 4 + 0][cc];
            float b1 = Bs[ty * 4 + 1][cc];
            float b2 = Bs[ty * 4 + 2][cc];
            float b3 = Bs[ty * 4 + 3][cc];
            acc[0][0] += a.x * b0; acc[0][1] += a.x * b1; acc[0][2] += a.x * b2; acc[0][3] += a.x * b3;
            acc[1][0] += a.y * b0; acc[1][1] += a.y * b1; acc[1][2] += a.y * b2; acc[1][3] += a.y * b3;
            acc[2][0] += a.z * b0; acc[2][1] += a.z * b1; acc[2][2] += a.z * b2; acc[2][3] += a.z * b3;
            acc[3][0] += a.w * b0; acc[3][1] += a.w * b1; acc[3][2] += a.w * b2; acc[3][3] += a.w * b3;
        }
        __syncthreads();
    }

    float bj[4] = { bias[ty*4], bias[ty*4+1], bias[ty*4+2], bias[ty*4+3] };
#pragma unroll
    for (int i = 0; i < 4; i++) {
        int n = n0 + tx * 4 + i;
        uint4 hi, lo;
        float v0 = acc[i][0] + bj[0];
        float v1 = acc[i][1] + bj[1];
        float v2 = acc[i][2] + bj[2];
        float v3 = acc[i][3] + bj[3];
        hi.x = f2tf32(v0); lo.x = f2tf32(v0 - __uint_as_float(hi.x));
        hi.y = f2tf32(v1); lo.y = f2tf32(v1 - __uint_as_float(hi.y));
        hi.z = f2tf32(v2); lo.z = f2tf32(v2 - __uint_as_float(hi.z));
        hi.w = f2tf32(v3); lo.w = f2tf32(v3 - __uint_as_float(hi.w));
        *(uint4*)(o_hi + ((size_t)b * NN + n) * DQK + ty * 4) = hi;
        *(uint4*)(o_lo + ((size_t)b * NN + n) * DQK + ty * 4) = lo;
    }
}

// ---------------------------------------------------------------------------
// proj_v: V projection, tf32-rounded, TRANSPOSED store [b][c][n]
// ---------------------------------------------------------------------------
__global__ __launch_bounds__(256) void proj_v(
    const float* __restrict__ X, const float* __restrict__ W,
    const float* __restrict__ bias, float* __restrict__ outT)
{
    const int b  = blockIdx.z;
    const int n0 = blockIdx.x * 128;
    const int j0 = blockIdx.y * 32;
    const int t  = threadIdx.x;
    const int tx = t & 31;
    const int ty = t >> 5;

    __shared__ float As[32][128];
    __shared__ float Bs[32][32];

    float acc[4][4];
#pragma unroll
    for (int i = 0; i < 4; i++)
#pragma unroll
        for (int u = 0; u < 4; u++) acc[i][u] = 0.f;

    const float* Xb = X + b * CC * NN;
    for (int c0 = 0; c0 < CC; c0 += 32) {
#pragma unroll
        for (int i = 0; i < 4; i++) {
            int idx = t + 256 * i;
            int cc  = idx >> 5;
            int nn  = (idx & 31) * 4;
            *(float4*)&As[cc][nn] = *(const float4*)(Xb + (c0 + cc) * NN + n0 + nn);
        }
        {
            int jj = t >> 3;
            int c4 = (t & 7) * 4;
            *(float4*)&Bs[jj][c4] = *(const float4*)(W + (j0 + jj) * CC + c0 + c4);
        }
        __syncthreads();
#pragma unroll
        for (int cc = 0; cc < 32; cc++) {
            float4 a = *(const float4*)&As[cc][tx * 4];
            float b0 = Bs[ty * 4 + 0][cc];
            float b1 = Bs[ty * 4 + 1][cc];
            float b2 = Bs[ty * 4 + 2][cc];
            float b3 = Bs[ty * 4 + 3][cc];
            acc[0][0] += a.x * b0; acc[0][1] += a.x * b1; acc[0][2] += a.x * b2; acc[0][3] += a.x * b3;
            acc[1][0] += a.y * b0; acc[1][1] += a.y * b1; acc[1][2] += a.y * b2; acc[1][3] += a.y * b3;
            acc[2][0] += a.z * b0; acc[2][1] += a.z * b1; acc[2][2] += a.z * b2; acc[2][3] += a.z * b3;
            acc[3][0] += a.w * b0; acc[3][1] += a.w * b1; acc[3][2] += a.w * b2; acc[3][3] += a.w * b3;
        }
        __syncthreads();
    }

    // transposed tf32 store: outT[(b*CC + j)*NN + n], float4 over n
#pragma unroll
    for (int jj = 0; jj < 4; jj++) {
        int j = j0 + ty * 4 + jj;
        float bjv = bias[j];
        uint4 r;
        r.x = f2tf32(acc[0][jj] + bjv);
        r.y = f2tf32(acc[1][jj] + bjv);
        r.z = f2tf32(acc[2][jj] + bjv);
        r.w = f2tf32(acc[3][jj] + bjv);
        *(uint4*)(outT + ((size_t)b * CC + j) * NN + n0 + tx * 4) = r;
    }
}

// ---------------------------------------------------------------------------
// Flash attention: O^T = V^T P^T, all operands fragment-packed + ldmatrix.
//   S map : warp w: rows ms=(w&7)*16, keys nh=(w>>3)*16.
//   PV map: warp w: channels cgp=(w>>2)*64, rows rgp=(w&3)*32.
// ---------------------------------------------------------------------------
__global__ __launch_bounds__(THREADS) void flash_kernel(float* __restrict__ out)
{
    extern __shared__ float sm[];
    const uint32_t smem = smem_u32(sm);

    const int b    = blockIdx.y;
    const int n0   = blockIdx.x * TQ;
    const int t    = threadIdx.x;
    const int w    = t >> 5;
    const int lane = t & 31;
    const int gid  = lane >> 2;
    const int tid  = lane & 3;
    const int grp  = lane >> 3;
    const int row8 = lane & 7;
    // S mapping
    const int ms = (w & 7) * 16;
    const int rblkS = w & 7;
    // PV mapping
    const int cgp = (w >> 2) * 64;
    const int rgp = (w & 3) * 32;

    const float* gqh = g_qh + ((size_t)b * NN + n0) * DQK;
    const float* gql = g_ql + ((size_t)b * NN + n0) * DQK;
    const float* gkh = g_kh + (size_t)b * NN * DQK;
    const float* gkl = g_kl + (size_t)b * NN * DQK;
    const float* gvT = g_vT + (size_t)b * CC * NN;

    float*    Qlo  = sm + OFF_QLO;
    float*    lsum = sm + OFF_LSUM;
    uint32_t* Pb[2] = { (uint32_t*)(sm + OFF_P(0)), (uint32_t*)(sm + OFF_P(1)) };

    // ldmatrix lane-local byte offsets
    const uint32_t lm_gen = (grp >> 1) * 1024 + (grp & 1) * 128 + row8 * 16;
    // Qlo (R15 packing): matrix order a0,a1,a2,a3 within 512B group
    const uint32_t qlo_lm = smem + OFF_QLO * 4 + rblkS * 2048 + grp * 128 + row8 * 16;
    // K planes: + (w>>3)*2048 for the warp's key half
    const uint32_t khlm[2] = {
        smem + OFF_KH(0) * 4 + (w >> 3) * 2048 + lm_gen,
        smem + OFF_KH(1) * 4 + (w >> 3) * 2048 + lm_gen };
    // PV A (V^T): + cgp*128 base
    const uint32_t vlm[3] = {
        smem + OFF_V(0) * 4 + cgp * 128 + (grp & 1) * 1024 + (grp >> 1) * 128 + row8 * 16,
        smem + OFF_V(1) * 4 + cgp * 128 + (grp & 1) * 1024 + (grp >> 1) * 128 + row8 * 16,
        smem + OFF_V(2) * 4 + cgp * 128 + (grp & 1) * 1024 + (grp >> 1) * 128 + row8 * 16 };
    // PV B (P^T): + rgp*128 base
    const uint32_t plm[2] = {
        smem + OFF_P(0) * 4 + rgp * 128 + lm_gen,
        smem + OFF_P(1) * 4 + rgp * 128 + lm_gen };

    // P writer base (word index into Pb): mid = rb*8 + (nh/8+j)*2 + (tid>>1)
    const int pw_base = (w & 7) * 512 + (w >> 3) * 128 + (tid >> 1) * 32
                      + gid * 4 + (tid & 1) * 2;

    // --- Q fragments: qhi regs (all warps); qlo fragment-packed (warps 0-7) ---
    uint32_t qhi[4][4];
    {
        const float* q0 = gqh + (size_t)(ms + gid) * DQK;
        const float* q1 = q0 + 8 * DQK;
        const float* l0 = gql + (size_t)(ms + gid) * DQK;
        const float* l1 = l0 + 8 * DQK;
#pragma unroll
        for (int kk = 0; kk < 4; kk++) {
            qhi[kk][0] = __float_as_uint(__ldg(q0 + kk * 8 + tid));
            qhi[kk][1] = __float_as_uint(__ldg(q1 + kk * 8 + tid));
            qhi[kk][2] = __float_as_uint(__ldg(q0 + kk * 8 + tid + 4));
            qhi[kk][3] = __float_as_uint(__ldg(q1 + kk * 8 + tid + 4));
            if (w < 8) {
                int bw = (rblkS * 4 + kk) * 128 + gid * 4 + tid;
                Qlo[bw]      = __ldg(l0 + kk * 8 + tid);
                Qlo[bw + 32] = __ldg(l1 + kk * 8 + tid);
                Qlo[bw + 64] = __ldg(l0 + kk * 8 + tid + 4);
                Qlo[bw + 96] = __ldg(l1 + kk * 8 + tid + 4);
            }
        }
    }

    float acc[4][4][4];     // [it: c-tile][jt: r-tile][frag]
#pragma unroll
    for (int it = 0; it < 4; it++)
#pragma unroll
        for (int jt = 0; jt < 4; jt++)
#pragma unroll
            for (int u = 0; u < 4; u++) acc[it][jt][u] = 0.f;

    float lrun_lo = 0.f, lrun_hi = 0.f;

    // --- staging (fragment-packed dst) ---
    auto stage_k = [&](int kt_idx, int bf) {
        const int plane = t >> 8;
        const int m = (t >> 3) & 31;
        const int c = t & 7;
        const int mid = (m >> 3) * 8 + (c >> 1) * 2 + (c & 1);
        const float* src = (plane ? gkl : gkh) + (size_t)(kt_idx * KT + m) * DQK + c * 4;
        const uint32_t dstw = (uint32_t)(4096 + bf * 2048 + plane * 1024 + mid * 32 + (m & 7) * 4);
        cp16(smem + dstw * 4, src);
    };
    auto stage_v = [&](int kt_idx, int bf) {
        const uint32_t base = smem + OFF_V(bf) * 4;
#pragma unroll
        for (int i = 0; i < 4; i++) {
            int ch = t + THREADS * i;           // 0..2047
            int c  = ch >> 3;
            int m4 = ch & 7;
            int mid = (c >> 3) * 8 + (m4 >> 1) * 2 + (m4 & 1);
            cp16(base + (mid * 32 + (c & 7) * 4) * 4,
                 gvT + (size_t)c * NN + kt_idx * KT + m4 * 4);
        }
    };

    // --- S phase: split-tf32 3-pass; all operands via ldmatrix ---
    auto s_phase = [&](uint32_t klm, uint32_t* Pw) {
        float sf[2][4];
#pragma unroll
        for (int j = 0; j < 2; j++)
#pragma unroll
            for (int u = 0; u < 4; u++) sf[j][u] = 0.f;

#pragma unroll
        for (int kk = 0; kk < 4; kk++) {
            uint32_t ql0, ql1, ql2, ql3;
            ldm_x4(ql0, ql1, ql2, ql3, qlo_lm + kk * 512);
            uint32_t bh00, bh10, bh01, bh11;
            ldm_x4(bh00, bh10, bh01, bh11, klm + kk * 256);
            uint32_t bl00, bl10, bl01, bl11;
            ldm_x4(bl00, bl10, bl01, bl11, klm + 4096 + kk * 256);
            mma_tf32(sf[0], qhi[kk][0], qhi[kk][1], qhi[kk][2], qhi[kk][3], bh00, bh10);
            mma_tf32(sf[0], ql0, ql1, ql2, ql3, bh00, bh10);
            mma_tf32(sf[0], qhi[kk][0], qhi[kk][1], qhi[kk][2], qhi[kk][3], bl00, bl10);
            mma_tf32(sf[1], qhi[kk][0], qhi[kk][1], qhi[kk][2], qhi[kk][3], bh01, bh11);
            mma_tf32(sf[1], ql0, ql1, ql2, ql3, bh01, bh11);
            mma_tf32(sf[1], qhi[kk][0], qhi[kk][1], qhi[kk][2], qhi[kk][3], bl01, bl11);
        }

#pragma unroll
        for (int j = 0; j < 2; j++) {
            float e0 = __expf(sf[j][0]);
            float e1 = __expf(sf[j][1]);
            float e2 = __expf(sf[j][2]);
            float e3 = __expf(sf[j][3]);
            lrun_lo += e0 + e1;
            lrun_hi += e2 + e3;
            uint2 plo, phi;
            plo.x = f2tf32(e0); plo.y = f2tf32(e1);
            phi.x = f2tf32(e2); phi.y = f2tf32(e3);
            int idx = pw_base + j * 64;
            *(uint2*)&Pw[idx]       = plo;   // rows ms+gid   (rb)
            *(uint2*)&Pw[idx + 256] = phi;   // rows ms+gid+8 (rb+1)
        }
    };

    // --- PV phase: O^T += V^T P^T, all frags via ldmatrix ---
    auto pv_phase = [&](uint32_t vbase, uint32_t pbase) {
#pragma unroll
        for (int ks = 0; ks < 4; ks++) {
            uint32_t b0[4], b1[4];
#pragma unroll
            for (int p = 0; p < 2; p++) {
                uint32_t t0, t1, t2, t3;
                ldm_x4(t0, t1, t2, t3, pbase + p * 2048 + ks * 256);
                b0[2 * p] = t0; b1[2 * p] = t1;
                b0[2 * p + 1] = t2; b1[2 * p + 1] = t3;
            }
#pragma unroll
            for (int it = 0; it < 4; it++) {
                uint32_t a0, a1, a2, a3;
                ldm_x4(a0, a1, a2, a3, vbase + it * 2048 + ks * 256);
#pragma unroll
                for (int jt = 0; jt < 4; jt++)
                    mma_tf32(acc[it][jt], a0, a1, a2, a3, b0[jt], b1[jt]);
            }
        }
    };

    // --- prologue ---
    stage_k(0, 0);
    stage_k(1, 1);
    stage_v(0, 0);
    stage_v(1, 1);
    CP_COMMIT();
    CP_WAIT0();
    __syncthreads();
    s_phase(khlm[0], Pb[0]);
    __syncthreads();

    // --- main loop ---
    int v_rd = 0, v_wr = 2;
    for (int kt = 0; kt < NKT; kt++) {
        const int buf = kt & 1;

        if (kt + 2 < NKT) {
            stage_k(kt + 2, buf);
            stage_v(kt + 2, v_wr);
        }
        CP_COMMIT();

        pv_phase(vlm[v_rd], plm[buf]);

        CP_WAIT1();                      // group(kt-1): K(kt+1), V(kt+1) done

        if (kt + 1 < NKT)
            s_phase(khlm[buf ^ 1], Pb[buf ^ 1]);

        __syncthreads();
        v_rd = (v_rd == 2) ? 0 : v_rd + 1;
        v_wr = (v_wr == 2) ? 0 : v_wr + 1;
    }

    // --- row-sum reduction ---
    lrun_lo += __shfl_xor_sync(0xffffffffu, lrun_lo, 1);
    lrun_lo += __shfl_xor_sync(0xffffffffu, lrun_lo, 2);
    lrun_hi += __shfl_xor_sync(0xffffffffu, lrun_hi, 1);
    lrun_hi += __shfl_xor_sync(0xffffffffu, lrun_hi, 2);
    if (tid == 0) {
        lsum[(w >> 3) * 128 + ms + gid]     = lrun_lo;
        lsum[(w >> 3) * 128 + ms + gid + 8] = lrun_hi;
    }
    __syncthreads();
    if (t < 128) Qlo[t] = 1.f / (lsum[t] + lsum[128 + t]);   // reuse Qlo as inv
    __syncthreads();

    // --- epilogue: O^T fragments -> out[b][c][n0+r], float2 along r ---
    float* ob = out + (size_t)b * CC * NN + n0;
#pragma unroll
    for (int it = 0; it < 4; it++) {
        const int c_lo = cgp + it * 16 + gid;
        const int c_hi = c_lo + 8;
#pragma unroll
        for (int jt = 0; jt < 4; jt++) {
            const int r0 = rgp + jt * 8 + tid * 2;
            const float i0 = Qlo[r0];
            const float i1 = Qlo[r0 + 1];
            float2 lo, hi;
            lo.x = acc[it][jt][0] * i0; lo.y = acc[it][jt][1] * i1;
            hi.x = acc[it][jt][2] * i0; hi.y = acc[it][jt][3] * i1;
            *(float2*)(ob + (size_t)c_lo * NN + r0) = lo;
            *(float2*)(ob + (size_t)c_hi * NN + r0) = hi;
        }
    }
}

// ---------------------------------------------------------------------------
extern "C" void kernel_launch(void* const* d_in, const int* in_sizes, int n_in,
                              void* d_out, int out_size)
{
    const float* f1 = (const float*)d_in[0];
    const float* f2 = (const float*)d_in[1];
    const float* Wq = (const float*)d_in[2];
    const float* bq = (const float*)d_in[3];
    const float* Wk = (const float*)d_in[4];
    const float* bk = (const float*)d_in[5];
    const float* Wv = (const float*)d_in[6];
    const float* bv = (const float*)d_in[7];
    float* out = (float*)d_out;

    float *qh, *ql, *kh, *kl, *vT;
    cudaGetSymbolAddress((void**)&qh, g_qh);
    cudaGetSymbolAddress((void**)&ql, g_ql);
    cudaGetSymbolAddress((void**)&kh, g_kh);
    cudaGetSymbolAddress((void**)&kl, g_kl);
    cudaGetSymbolAddress((void**)&vT, g_vT);

    const int smem_bytes = SMEM_FLOATS * (int)sizeof(float);
    cudaFuncSetAttribute(flash_kernel,
                         cudaFuncAttributeMaxDynamicSharedMemorySize, smem_bytes);

    proj_qk<<<dim3(NN / 128, 1, BB), 256>>>(f1, Wq, bq, qh, ql);
    proj_qk<<<dim3(NN / 128, 1, BB), 256>>>(f2, Wk, bk, kh, kl);
    proj_v <<<dim3(NN / 128, 8, BB), 256>>>(f2, Wv, bv, vT);
    flash_kernel<<<dim3(NN / TQ, BB), THREADS, smem_bytes>>>(out);
}